// round 9
// baseline (speedup 1.0000x reference)
#include <cuda_runtime.h>
#include <math.h>
#include <stdint.h>

#define N_TOK 16384
#define D 512
#define VOCAB 96
#define CHUNK 16                 // tokens per main block
#define MAXCHUNKS 18             // 288 >= max bucket size (mean 170.7, sd 13)

// ---------------- device scratch ----------------
__device__ float4 g_U[VOCAB * D];    // (u1r, u1i, u2r, u2i)
__device__ float4 g_V[VOCAB * D];    // (V1r, V1i, V2r, V2i) = U @ W^T
__device__ float4 g_S[VOCAB];        // (S11, S22, S12r, S12i)
__device__ float4 g_phtab[D];        // cosP, sinP, cos2P, sin2P
__device__ float4 g_cols[D];         // bias, gamma, beta, 0
__device__ float4 g_wf[N_TOK];       // wf1r, wf1i, wf2r, wf2i
__device__ float4 g_tokA[VOCAB];     // cos(cpm), sin(cpm), cos(1.3cpm), sin(1.3cpm)
__device__ float2 g_tokB[VOCAB];     // cos(.7cpm), sin(.7cpm)
__device__ int    g_perm[N_TOK];     // token ids grouped by char
__device__ int    g_off[VOCAB];      // bucket start
__device__ int    g_cnt[VOCAB];      // bucket size

// ---------------- K0: all trig ----------------
// grid 112 x 256 = 28672 threads.
// [0,12288): U entries (one thread = one d x 4 chars, recurrence)
// [12288, 28672): per-token wf (16384)
// sub-ranges of U part also fill d-tables (gid<512) and char trig (512<=gid<608)
__global__ __launch_bounds__(256) void setup_kernel(const int* __restrict__ char_idx,
                                                    const int* __restrict__ positions,
                                                    const float* __restrict__ bias,
                                                    const float* __restrict__ gamma,
                                                    const float* __restrict__ beta_ln) {
    const int gid = blockIdx.x * blockDim.x + threadIdx.x;
    const float PI = 3.14159265358979323846f;
    const float TH1 = 2.0f * PI / ((float)VOCAB * (float)D);
    const float TH2 = 4.0f * PI * 1.7f / ((float)VOCAB * (float)D);

    if (gid < 12288) {
        const int d = gid & 511;
        const int c0 = (gid >> 9) * 4;

        // d-only filter / weights
        float kv = (float)d + 1.0f;
        float s1, c1, s2, c2;
        sincosf(1.5f * atanf(logf(kv + 1e-10f)), &s1, &c1);
        sincosf(0.8f * sinf(0.1f * kv), &s2, &c2);
        float fr = 0.7f * c1 + 0.3f * c2;
        float fi = 0.7f * s1 + 0.3f * s2;
        float w1 = 0.6f + 0.4f * sinf(0.1f * (float)d);
        float w2 = 0.4f + 0.6f * cosf(0.15f * (float)d);

        float th1 = TH1 * (float)d;
        float th2 = TH2 * (float)d;
        float s, co;
        sincosf(th1 * (float)c0, &s, &co);
        float m1r = co, m1i = s;
        sincosf(th1, &s, &co);
        float e1r = co, e1i = s;
        sincosf(th2 * (float)c0, &s, &co);
        float m2r = co, m2i = s;
        sincosf(th2, &s, &co);
        float e2r = co, e2i = s;

        #pragma unroll
        for (int k = 0; k < 4; k++) {
            float u1r = w1 * (m1r * fr - m1i * fi);
            float u1i = w1 * (m1r * fi + m1i * fr);
            float u2r = w2 * (m2r * fr - m2i * fi);
            float u2i = w2 * (m2r * fi + m2i * fr);
            g_U[(c0 + k) * D + d] = make_float4(u1r, u1i, u2r, u2i);
            float t1r = m1r * e1r - m1i * e1i;
            float t1i = m1r * e1i + m1i * e1r;
            m1r = t1r; m1i = t1i;
            float t2r = m2r * e2r - m2i * e2i;
            float t2i = m2r * e2i + m2i * e2r;
            m2r = t2r; m2i = t2i;
        }

        if (gid < D) {
            float ph = 2.0f * PI * (float)gid * (1.0f / (float)D);
            float sp, cp, s2p, c2p;
            sincosf(ph, &sp, &cp);
            sincosf(2.0f * ph, &s2p, &c2p);
            g_phtab[gid] = make_float4(cp, sp, c2p, s2p);
            g_cols[gid] = make_float4(bias[gid], gamma[gid], beta_ln[gid], 0.f);
        }
        if (gid >= 512 && gid < 512 + VOCAB) {
            int cc = gid - 512;
            float cpm = (float)cc * 0.01f;
            float s0, c0_, sb, cb, sc, ccc;
            sincosf(cpm, &s0, &c0_);
            sincosf(cpm * 1.3f, &sb, &cb);
            sincosf(cpm * 0.7f, &sc, &ccc);
            g_tokA[cc] = make_float4(c0_, s0, cb, sb);
            g_tokB[cc] = make_float2(ccc, sc);
        }
    } else {
        const int n = gid - 12288;   // 0..16383
        int ci = char_idx[n];
        float lam = (float)ci * (1.0f / (float)VOCAB);
        float t = (float)positions[n] * 0.01f;
        float omega = 2.0f * PI * 1.5f;
        float kwav = 2.0f * PI / 1.7f;
        float ph1 = omega * t - kwav * lam + 0.8f * lam * lam;
        float ph2 = omega * t * 1.5f - kwav * lam * 0.7f + 0.8f * lam * lam * 1.3f;
        float a1 = sinf(omega * t + 1.5f * lam);
        float a2 = cosf(omega * t * 0.8f + 1.5f * lam * 1.2f);
        float s, cc;
        sincosf(ph1, &s, &cc);
        float wf1r = a1 * cc, wf1i = a1 * s;
        sincosf(ph2, &s, &cc);
        float wf2r = a2 * cc, wf2i = a2 * s;
        g_wf[n] = make_float4(wf1r, wf1i, wf2r, wf2i);
    }
}

// ---------------- K1: deterministic bucket scatter (no atomics) ----------------
// 96 blocks (one per char value), 256 threads; each thread owns 64 contiguous tokens.
__global__ __launch_bounds__(256) void scatter_kernel(const int* __restrict__ char_idx) {
    const int c = blockIdx.x;
    const int t = threadIdx.x;

    __shared__ int s_eq[256], s_lt[256];

    int eq = 0, lt = 0;
    const int base = t * 64;
    #pragma unroll 4
    for (int j = 0; j < 64; j++) {
        int ci = __ldg(&char_idx[base + j]);
        eq += (ci == c);
        lt += (ci < c);
    }
    s_eq[t] = eq;
    s_lt[t] = lt;
    __syncthreads();

    // Hillis-Steele inclusive scan on s_eq; full reduce on s_lt
    #pragma unroll
    for (int off = 1; off < 256; off <<= 1) {
        int ve = (t >= off) ? s_eq[t - off] : 0;
        int vl = (t >= off) ? s_lt[t - off] : 0;
        __syncthreads();
        s_eq[t] += ve;
        s_lt[t] += vl;
        __syncthreads();
    }
    const int off_c = s_lt[255];                 // #{tokens with char < c}
    const int my_start = off_c + s_eq[t] - eq;   // exclusive prefix
    if (t == 255) {
        g_off[c] = off_c;
        g_cnt[c] = s_eq[255];
    }

    int w = my_start;
    for (int j = 0; j < 64; j++) {
        int ci = __ldg(&char_idx[base + j]);
        if (ci == c) g_perm[w++] = base + j;
    }
}

// ---------------- K2: tiled V gemm + Gram sums, 2 chars per block ----------------
__global__ __launch_bounds__(128) void vgemm_kernel(const float* __restrict__ W) {
    const int c0 = blockIdx.x * 2;
    const int q = blockIdx.y;
    const int tid = threadIdx.x;

    __shared__ float4 su[2][D];
    __shared__ float tile[128][33];
    __shared__ float sm[4][4];

    #pragma unroll
    for (int l = 0; l < 4; l++) {
        su[0][tid + l * 128] = __ldg(&g_U[(c0 + 0) * D + tid + l * 128]);
        su[1][tid + l * 128] = __ldg(&g_U[(c0 + 1) * D + tid + l * 128]);
    }
    __syncthreads();

    if (q == 0) {
        #pragma unroll
        for (int cc = 0; cc < 2; cc++) {
            float s11 = 0.f, s22 = 0.f, s12r = 0.f, s12i = 0.f;
            #pragma unroll
            for (int l = 0; l < 4; l++) {
                float4 u = su[cc][tid + l * 128];
                s11 += u.x * u.x + u.y * u.y;
                s22 += u.z * u.z + u.w * u.w;
                s12r += u.x * u.z + u.y * u.w;
                s12i += u.y * u.z - u.x * u.w;
            }
            #pragma unroll
            for (int o = 16; o > 0; o >>= 1) {
                s11 += __shfl_xor_sync(0xffffffffu, s11, o);
                s22 += __shfl_xor_sync(0xffffffffu, s22, o);
                s12r += __shfl_xor_sync(0xffffffffu, s12r, o);
                s12i += __shfl_xor_sync(0xffffffffu, s12i, o);
            }
            if ((tid & 31) == 0) {
                int w = tid >> 5;
                sm[0][w] = s11; sm[1][w] = s22; sm[2][w] = s12r; sm[3][w] = s12i;
            }
            __syncthreads();
            if (tid == 0) {
                g_S[c0 + cc] = make_float4(sm[0][0] + sm[0][1] + sm[0][2] + sm[0][3],
                                           sm[1][0] + sm[1][1] + sm[1][2] + sm[1][3],
                                           sm[2][0] + sm[2][1] + sm[2][2] + sm[2][3],
                                           sm[3][0] + sm[3][1] + sm[3][2] + sm[3][3]);
            }
            __syncthreads();
        }
    }

    const int dpbase = q * 128;
    float a1r = 0.f, a1i = 0.f, a2r = 0.f, a2i = 0.f;
    float b1r = 0.f, b1i = 0.f, b2r = 0.f, b2i = 0.f;

    #pragma unroll 1
    for (int chunk = 0; chunk < 16; chunk++) {
        const int dk = chunk * 32;
        __syncthreads();
        #pragma unroll
        for (int l = 0; l < 8; l++) {
            int f = tid + l * 128;
            int row = f >> 3, col4 = (f & 7) * 4;
            float4 w = *(const float4*)(W + (size_t)(dpbase + row) * D + dk + col4);
            tile[row][col4 + 0] = w.x;
            tile[row][col4 + 1] = w.y;
            tile[row][col4 + 2] = w.z;
            tile[row][col4 + 3] = w.w;
        }
        __syncthreads();
        #pragma unroll
        for (int k = 0; k < 32; k++) {
            float wv = tile[tid][k];
            float4 u = su[0][dk + k];
            float4 v = su[1][dk + k];
            a1r = fmaf(u.x, wv, a1r);
            a1i = fmaf(u.y, wv, a1i);
            a2r = fmaf(u.z, wv, a2r);
            a2i = fmaf(u.w, wv, a2i);
            b1r = fmaf(v.x, wv, b1r);
            b1i = fmaf(v.y, wv, b1i);
            b2r = fmaf(v.z, wv, b2r);
            b2i = fmaf(v.w, wv, b2i);
        }
    }
    g_V[(c0 + 0) * D + dpbase + tid] = make_float4(a1r, a1i, a2r, a2i);
    g_V[(c0 + 1) * D + dpbase + tid] = make_float4(b1r, b1i, b2r, b2i);
}

// ---------------- K3: bucketed main — 16 same-char tokens per block ----------------
// grid (96, MAXCHUNKS), 512 threads; warp = token; V row staged in smem.
__global__ __launch_bounds__(512, 2) void main_kernel(const float* __restrict__ noise,
                                                      const float* __restrict__ sem,
                                                      float4* __restrict__ out) {
    const int c = blockIdx.x;
    const int cnt = g_cnt[c];
    const int start = blockIdx.y * CHUNK;
    if (start >= cnt) return;

    __shared__ float4 sv[D];

    const int tid = threadIdx.x;
    const int w = tid >> 5;        // warp = token slot
    const int lane = tid & 31;

    sv[tid] = __ldg(&g_V[c * D + tid]);
    __syncthreads();

    const int slot = start + w;
    if (slot >= cnt) return;
    const int n = g_perm[g_off[c] + slot];

    // per-token coefficients
    const float4 wf = __ldg(&g_wf[n]);
    const float4 S = __ldg(&g_S[c]);
    float n1 = wf.x * wf.x + wf.y * wf.y;
    float n2 = wf.z * wf.z + wf.w * wf.w;
    float Ar = wf.x * wf.z + wf.y * wf.w;
    float Ai = wf.y * wf.z - wf.x * wf.w;
    float nrm2 = n1 * S.x + n2 * S.y + 2.0f * (Ar * S.z - Ai * S.w);
    float rinv = 1.0f / (sqrtf(nrm2) + 1e-8f);
    const float ct = 0.995004165278025766f;
    const float st = 0.0998334166468281523f;
    const float p1 = (wf.x * ct - wf.y * st) * rinv;
    const float q1 = -(wf.y * ct + wf.x * st) * rinv;
    const float p2 = (wf.z * ct - wf.w * st) * rinv;
    const float q2 = -(wf.w * ct + wf.z * st) * rinv;

    // pass 1: xw + LN stats; prefetch noise into regs
    const float* nrow = noise + (size_t)n * D;
    float nz[16];
    float s = 0.f, ss = 0.f;
    #pragma unroll
    for (int j = 0; j < 16; j++) {
        const int d = j * 32 + lane;
        float4 v = sv[d];
        nz[j] = __ldcs(&nrow[d]);
        float x = fmaf(p1, v.x, fmaf(q1, v.y, fmaf(p2, v.z, q2 * v.w)))
                + __ldg(&g_cols[d]).x;
        s += x;
        ss = fmaf(x, x, ss);
    }
    #pragma unroll
    for (int o = 16; o > 0; o >>= 1) {
        s += __shfl_xor_sync(0xffffffffu, s, o);
        ss += __shfl_xor_sync(0xffffffffu, ss, o);
    }
    const float mu = s * (1.0f / (float)D);
    const float rstd = rsqrtf(ss * (1.0f / (float)D) - mu * mu + 1e-5f);

    const float sw0 = __ldg(&sem[c * 4 + 0]);
    const float sw1 = __ldg(&sem[c * 4 + 1]);
    const float sw2 = __ldg(&sem[c * 4 + 2]);
    const float4 tA = __ldg(&g_tokA[c]);
    const float2 tB = __ldg(&g_tokB[c]);

    float4* orow = out + (size_t)n * D;

    // pass 2: recompute xw (bit-identical), transform, store
    #pragma unroll
    for (int j = 0; j < 16; j++) {
        const int d = j * 32 + lane;
        float4 v = sv[d];
        float4 col = __ldg(&g_cols[d]);
        float x = fmaf(p1, v.x, fmaf(q1, v.y, fmaf(p2, v.z, q2 * v.w))) + col.x;
        float y = (x - mu) * rstd * col.y + col.z + 0.01f * nz[j];
        float4 ph = __ldg(&g_phtab[d]);
        float4 o;
        o.x = y;
        o.y = y * sw0 * (ph.x * tA.x - ph.y * tA.y);   // cos(phase + cpm)
        o.z = y * sw1 * (ph.y * tA.z + ph.x * tA.w);   // sin(phase + 1.3cpm)
        o.w = y * sw2 * (ph.z * tB.x - ph.w * tB.y);   // cos(2phase + 0.7cpm)
        __stcs(&orow[d], o);
    }
}

// ---------------- launch ----------------
extern "C" void kernel_launch(void* const* d_in, const int* in_sizes, int n_in,
                              void* d_out, int out_size) {
    const int*   char_idx  = (const int*)d_in[0];
    const int*   positions = (const int*)d_in[1];
    const float* W         = (const float*)d_in[2];
    const float* b         = (const float*)d_in[3];
    const float* gamma     = (const float*)d_in[4];
    const float* beta_ln   = (const float*)d_in[5];
    const float* noise     = (const float*)d_in[6];
    const float* sem       = (const float*)d_in[7];
    float4* out = (float4*)d_out;

    setup_kernel<<<112, 256>>>(char_idx, positions, b, gamma, beta_ln);
    scatter_kernel<<<VOCAB, 256>>>(char_idx);
    vgemm_kernel<<<dim3(VOCAB / 2, 4), 128>>>(W);
    main_kernel<<<dim3(VOCAB, MAXCHUNKS), 512>>>(noise, sem, out);
}

// round 10
// speedup vs baseline: 1.2532x; 1.2532x over previous
#include <cuda_runtime.h>
#include <math.h>
#include <stdint.h>

#define N_TOK 16384
#define D 512
#define VOCAB 96

// ---------------- device scratch ----------------
__device__ float4 g_U[VOCAB * D];    // (u1r, u1i, u2r, u2i)
__device__ float4 g_V[VOCAB * D];    // (V1r, V1i, V2r, V2i) = U @ W^T
__device__ float4 g_S[VOCAB];        // (S11, S22, S12r, S12i)
__device__ float4 g_phtab[D];        // cosP, sinP, cos2P, sin2P
__device__ float4 g_cols[D];         // bias, gamma, beta, 0
__device__ float4 g_wf[N_TOK];       // wf1r, wf1i, wf2r, wf2i
__device__ float4 g_tokA[VOCAB];     // cos(cpm), sin(cpm), cos(1.3cpm), sin(1.3cpm)
__device__ float2 g_tokB[VOCAB];     // cos(.7cpm), sin(.7cpm)

// ---------------- K0: all trig, fully parallel ----------------
// grid 112 x 256 = 28672 threads:
// [0,12288): U entries (one thread = one d x 4 chars, complex recurrence);
//            gid<512 also fills d-tables; 512<=gid<608 fills per-char trig
// [12288, 28672): per-token wf (16384)
__global__ __launch_bounds__(256) void setup_kernel(const int* __restrict__ char_idx,
                                                    const int* __restrict__ positions,
                                                    const float* __restrict__ bias,
                                                    const float* __restrict__ gamma,
                                                    const float* __restrict__ beta_ln) {
    const int gid = blockIdx.x * blockDim.x + threadIdx.x;
    const float PI = 3.14159265358979323846f;
    const float TH1 = 2.0f * PI / ((float)VOCAB * (float)D);
    const float TH2 = 4.0f * PI * 1.7f / ((float)VOCAB * (float)D);

    if (gid < 12288) {
        const int d = gid & 511;
        const int c0 = (gid >> 9) * 4;

        float kv = (float)d + 1.0f;
        float s1, c1, s2, c2;
        sincosf(1.5f * atanf(logf(kv + 1e-10f)), &s1, &c1);
        sincosf(0.8f * sinf(0.1f * kv), &s2, &c2);
        float fr = 0.7f * c1 + 0.3f * c2;
        float fi = 0.7f * s1 + 0.3f * s2;
        float w1 = 0.6f + 0.4f * sinf(0.1f * (float)d);
        float w2 = 0.4f + 0.6f * cosf(0.15f * (float)d);

        float th1 = TH1 * (float)d;
        float th2 = TH2 * (float)d;
        float s, co;
        sincosf(th1 * (float)c0, &s, &co);
        float m1r = co, m1i = s;
        sincosf(th1, &s, &co);
        float e1r = co, e1i = s;
        sincosf(th2 * (float)c0, &s, &co);
        float m2r = co, m2i = s;
        sincosf(th2, &s, &co);
        float e2r = co, e2i = s;

        #pragma unroll
        for (int k = 0; k < 4; k++) {
            float u1r = w1 * (m1r * fr - m1i * fi);
            float u1i = w1 * (m1r * fi + m1i * fr);
            float u2r = w2 * (m2r * fr - m2i * fi);
            float u2i = w2 * (m2r * fi + m2i * fr);
            g_U[(c0 + k) * D + d] = make_float4(u1r, u1i, u2r, u2i);
            float t1r = m1r * e1r - m1i * e1i;
            float t1i = m1r * e1i + m1i * e1r;
            m1r = t1r; m1i = t1i;
            float t2r = m2r * e2r - m2i * e2i;
            float t2i = m2r * e2i + m2i * e2r;
            m2r = t2r; m2i = t2i;
        }

        if (gid < D) {
            float ph = 2.0f * PI * (float)gid * (1.0f / (float)D);
            float sp, cp, s2p, c2p;
            sincosf(ph, &sp, &cp);
            sincosf(2.0f * ph, &s2p, &c2p);
            g_phtab[gid] = make_float4(cp, sp, c2p, s2p);
            g_cols[gid] = make_float4(bias[gid], gamma[gid], beta_ln[gid], 0.f);
        }
        if (gid >= 512 && gid < 512 + VOCAB) {
            int cc = gid - 512;
            float cpm = (float)cc * 0.01f;
            float s0, c0_, sb, cb, sc, ccc;
            sincosf(cpm, &s0, &c0_);
            sincosf(cpm * 1.3f, &sb, &cb);
            sincosf(cpm * 0.7f, &sc, &ccc);
            g_tokA[cc] = make_float4(c0_, s0, cb, sb);
            g_tokB[cc] = make_float2(ccc, sc);
        }
    } else {
        const int n = gid - 12288;
        int ci = char_idx[n];
        float lam = (float)ci * (1.0f / (float)VOCAB);
        float t = (float)positions[n] * 0.01f;
        float omega = 2.0f * PI * 1.5f;
        float kwav = 2.0f * PI / 1.7f;
        float ph1 = omega * t - kwav * lam + 0.8f * lam * lam;
        float ph2 = omega * t * 1.5f - kwav * lam * 0.7f + 0.8f * lam * lam * 1.3f;
        float a1 = sinf(omega * t + 1.5f * lam);
        float a2 = cosf(omega * t * 0.8f + 1.5f * lam * 1.2f);
        float s, cc;
        sincosf(ph1, &s, &cc);
        float wf1r = a1 * cc, wf1i = a1 * s;
        sincosf(ph2, &s, &cc);
        float wf2r = a2 * cc, wf2i = a2 * s;
        g_wf[n] = make_float4(wf1r, wf1i, wf2r, wf2i);
    }
}

// ---------------- K1: tiled V gemm + Gram sums, 2 chars per block ----------------
// grid (48, 4), 128 threads. Block (cg, q): chars {2cg, 2cg+1}, columns [q*128, q*128+128).
__global__ __launch_bounds__(128) void vgemm_kernel(const float* __restrict__ W) {
    const int c0 = blockIdx.x * 2;
    const int q = blockIdx.y;
    const int tid = threadIdx.x;

    __shared__ float4 su[2][D];
    __shared__ float tile[128][33];
    __shared__ float sm[4][4];

    #pragma unroll
    for (int l = 0; l < 4; l++) {
        su[0][tid + l * 128] = __ldg(&g_U[(c0 + 0) * D + tid + l * 128]);
        su[1][tid + l * 128] = __ldg(&g_U[(c0 + 1) * D + tid + l * 128]);
    }
    __syncthreads();

    if (q == 0) {
        #pragma unroll
        for (int cc = 0; cc < 2; cc++) {
            float s11 = 0.f, s22 = 0.f, s12r = 0.f, s12i = 0.f;
            #pragma unroll
            for (int l = 0; l < 4; l++) {
                float4 u = su[cc][tid + l * 128];
                s11 += u.x * u.x + u.y * u.y;
                s22 += u.z * u.z + u.w * u.w;
                s12r += u.x * u.z + u.y * u.w;
                s12i += u.y * u.z - u.x * u.w;
            }
            #pragma unroll
            for (int o = 16; o > 0; o >>= 1) {
                s11 += __shfl_xor_sync(0xffffffffu, s11, o);
                s22 += __shfl_xor_sync(0xffffffffu, s22, o);
                s12r += __shfl_xor_sync(0xffffffffu, s12r, o);
                s12i += __shfl_xor_sync(0xffffffffu, s12i, o);
            }
            if ((tid & 31) == 0) {
                int w = tid >> 5;
                sm[0][w] = s11; sm[1][w] = s22; sm[2][w] = s12r; sm[3][w] = s12i;
            }
            __syncthreads();
            if (tid == 0) {
                g_S[c0 + cc] = make_float4(sm[0][0] + sm[0][1] + sm[0][2] + sm[0][3],
                                           sm[1][0] + sm[1][1] + sm[1][2] + sm[1][3],
                                           sm[2][0] + sm[2][1] + sm[2][2] + sm[2][3],
                                           sm[3][0] + sm[3][1] + sm[3][2] + sm[3][3]);
            }
            __syncthreads();
        }
    }

    const int dpbase = q * 128;
    float a1r = 0.f, a1i = 0.f, a2r = 0.f, a2i = 0.f;
    float b1r = 0.f, b1i = 0.f, b2r = 0.f, b2i = 0.f;

    #pragma unroll 1
    for (int chunk = 0; chunk < 16; chunk++) {
        const int dk = chunk * 32;
        __syncthreads();
        #pragma unroll
        for (int l = 0; l < 8; l++) {
            int f = tid + l * 128;
            int row = f >> 3, col4 = (f & 7) * 4;
            float4 w = *(const float4*)(W + (size_t)(dpbase + row) * D + dk + col4);
            tile[row][col4 + 0] = w.x;
            tile[row][col4 + 1] = w.y;
            tile[row][col4 + 2] = w.z;
            tile[row][col4 + 3] = w.w;
        }
        __syncthreads();
        #pragma unroll
        for (int k = 0; k < 32; k++) {
            float wv = tile[tid][k];
            float4 u = su[0][dk + k];
            float4 v = su[1][dk + k];
            a1r = fmaf(u.x, wv, a1r);
            a1i = fmaf(u.y, wv, a1i);
            a2r = fmaf(u.z, wv, a2r);
            a2i = fmaf(u.w, wv, a2i);
            b1r = fmaf(v.x, wv, b1r);
            b1i = fmaf(v.y, wv, b1i);
            b2r = fmaf(v.z, wv, b2r);
            b2i = fmaf(v.w, wv, b2i);
        }
    }
    g_V[(c0 + 0) * D + dpbase + tid] = make_float4(a1r, a1i, a2r, a2i);
    g_V[(c0 + 1) * D + dpbase + tid] = make_float4(b1r, b1i, b2r, b2i);
}

// ---------------- K2: fused coef + xw + LayerNorm + noise + quaternion ----------
// One token per 128-thread group; 2 tokens per 256-thread block; 6 blocks/SM.
__global__ __launch_bounds__(256, 6) void main_kernel(const int* __restrict__ char_idx,
                                                      const float* __restrict__ noise,
                                                      const float* __restrict__ sem,
                                                      float4* __restrict__ out) {
    __shared__ float red_s[8], red_ss[8];

    const int tid = threadIdx.x;
    const int grp = tid >> 7;
    const int gt = tid & 127;
    const int lane = tid & 31;
    const int wid = tid >> 5;
    const int n = blockIdx.x * 2 + grp;

    // register-resident per-d tables (d = k*128 + gt, fixed per thread)
    float4 colr[4], phr[4];
    #pragma unroll
    for (int k = 0; k < 4; k++) {
        colr[k] = __ldg(&g_cols[k * 128 + gt]);
        phr[k]  = __ldg(&g_phtab[k * 128 + gt]);
    }

    const int c = __ldg(&char_idx[n]);
    const float4 wf = __ldg(&g_wf[n]);
    const float4 S = __ldg(&g_S[c]);

    // per-token coefficients
    float n1 = wf.x * wf.x + wf.y * wf.y;
    float n2 = wf.z * wf.z + wf.w * wf.w;
    float Ar = wf.x * wf.z + wf.y * wf.w;
    float Ai = wf.y * wf.z - wf.x * wf.w;
    float nrm2 = n1 * S.x + n2 * S.y + 2.0f * (Ar * S.z - Ai * S.w);
    float rinv = 1.0f / (sqrtf(nrm2) + 1e-8f);
    const float ct = 0.995004165278025766f;
    const float st = 0.0998334166468281523f;
    const float p1 = (wf.x * ct - wf.y * st) * rinv;
    const float q1 = -(wf.y * ct + wf.x * st) * rinv;
    const float p2 = (wf.z * ct - wf.w * st) * rinv;
    const float q2 = -(wf.w * ct + wf.z * st) * rinv;

    // 4 columns per thread, coalesced V reads; noise prefetched before reduction
    const float4* vrow = g_V + c * D;
    const float* nrow = noise + (size_t)n * D;
    float xw[4], nz[4];
    float s = 0.f, ss = 0.f;
    #pragma unroll
    for (int k = 0; k < 4; k++) {
        const int d = k * 128 + gt;
        float4 v = __ldg(&vrow[d]);
        nz[k] = __ldcs(&nrow[d]);
        float x = fmaf(p1, v.x, fmaf(q1, v.y, fmaf(p2, v.z, q2 * v.w))) + colr[k].x;
        xw[k] = x;
        s += x;
        ss = fmaf(x, x, ss);
    }
    #pragma unroll
    for (int o = 16; o > 0; o >>= 1) {
        s += __shfl_xor_sync(0xffffffffu, s, o);
        ss += __shfl_xor_sync(0xffffffffu, ss, o);
    }
    if (lane == 0) { red_s[wid] = s; red_ss[wid] = ss; }
    __syncthreads();
    const int rb = grp * 4;
    float ts = red_s[rb] + red_s[rb + 1] + red_s[rb + 2] + red_s[rb + 3];
    float tss = red_ss[rb] + red_ss[rb + 1] + red_ss[rb + 2] + red_ss[rb + 3];
    const float mu = ts * (1.0f / (float)D);
    const float rstd = rsqrtf(tss * (1.0f / (float)D) - mu * mu + 1e-5f);

    const float sw0 = __ldg(&sem[c * 4 + 0]);
    const float sw1 = __ldg(&sem[c * 4 + 1]);
    const float sw2 = __ldg(&sem[c * 4 + 2]);
    const float4 tA = __ldg(&g_tokA[c]);
    const float2 tB = __ldg(&g_tokB[c]);

    float4* orow = out + (size_t)n * D;

    #pragma unroll
    for (int k = 0; k < 4; k++) {
        const int d = k * 128 + gt;
        float y = (xw[k] - mu) * rstd * colr[k].y + colr[k].z + 0.01f * nz[k];
        float4 ph = phr[k];
        float4 o;
        o.x = y;
        o.y = y * sw0 * (ph.x * tA.x - ph.y * tA.y);   // cos(phase + cpm)
        o.z = y * sw1 * (ph.y * tA.z + ph.x * tA.w);   // sin(phase + 1.3cpm)
        o.w = y * sw2 * (ph.z * tB.x - ph.w * tB.y);   // cos(2phase + 0.7cpm)
        __stcs(&orow[d], o);
    }
}

// ---------------- launch ----------------
extern "C" void kernel_launch(void* const* d_in, const int* in_sizes, int n_in,
                              void* d_out, int out_size) {
    const int*   char_idx  = (const int*)d_in[0];
    const int*   positions = (const int*)d_in[1];
    const float* W         = (const float*)d_in[2];
    const float* b         = (const float*)d_in[3];
    const float* gamma     = (const float*)d_in[4];
    const float* beta_ln   = (const float*)d_in[5];
    const float* noise     = (const float*)d_in[6];
    const float* sem       = (const float*)d_in[7];
    float4* out = (float4*)d_out;

    setup_kernel<<<112, 256>>>(char_idx, positions, b, gamma, beta_ln);
    vgemm_kernel<<<dim3(VOCAB / 2, 4), 128>>>(W);
    main_kernel<<<N_TOK / 2, 256>>>(char_idx, noise, sem, out);
}

// round 11
// speedup vs baseline: 1.3202x; 1.0535x over previous
#include <cuda_runtime.h>
#include <math.h>
#include <stdint.h>

#define N_TOK 16384
#define D 512
#define VOCAB 96

// ---------------- device scratch ----------------
__device__ float4 g_V[VOCAB * D];    // (V1r, V1i, V2r, V2i) = U @ W^T
__device__ float4 g_S[VOCAB];        // (S11, S22, S12r, S12i)
__device__ float4 g_phtab[D];        // cosP, sinP, cos2P, sin2P
__device__ float4 g_cols[D];         // bias, gamma, beta, 0
__device__ float4 g_wf[N_TOK];       // wf1r, wf1i, wf2r, wf2i
__device__ float4 g_tokA[VOCAB];     // cos(cpm), sin(cpm), cos(1.3cpm), sin(1.3cpm)
__device__ float2 g_tokB[VOCAB];     // cos(.7cpm), sin(.7cpm)

// ---------------- K0: fused prep — U in-block + all tables + V gemm + Gram ----
// grid (48, 4), 128 threads. Block (cg, q): chars {2cg, 2cg+1},
// V columns [q*128, q*128+128). Flat gid covers wf/d-tables/char trig side jobs.
__global__ __launch_bounds__(128) void prep_kernel(const int* __restrict__ char_idx,
                                                   const int* __restrict__ positions,
                                                   const float* __restrict__ W,
                                                   const float* __restrict__ bias,
                                                   const float* __restrict__ gamma,
                                                   const float* __restrict__ beta_ln) {
    const int c0 = blockIdx.x * 2;
    const int q = blockIdx.y;
    const int tid = threadIdx.x;
    const int gid = (blockIdx.y * 48 + blockIdx.x) * 128 + tid;  // 0..24575
    const float PI = 3.14159265358979323846f;
    const float TH1 = 2.0f * PI / ((float)VOCAB * (float)D);
    const float TH2 = 4.0f * PI * 1.7f / ((float)VOCAB * (float)D);

    __shared__ float4 su[2][D];       // U rows for the two chars
    __shared__ float tile[128][33];   // W sub-tile, padded stride
    __shared__ float smr[4][4];

    // ---- U rows for chars c0, c0+1 (filter in regs, 4 d's per thread) ----
    #pragma unroll
    for (int l = 0; l < 4; l++) {
        const int d = tid + l * 128;
        float kv = (float)d + 1.0f;
        float s1, c1, s2, c2;
        sincosf(1.5f * atanf(logf(kv + 1e-10f)), &s1, &c1);
        sincosf(0.8f * sinf(0.1f * kv), &s2, &c2);
        float fr = 0.7f * c1 + 0.3f * c2;
        float fi = 0.7f * s1 + 0.3f * s2;
        float w1 = 0.6f + 0.4f * sinf(0.1f * (float)d);
        float w2 = 0.4f + 0.6f * cosf(0.15f * (float)d);
        float th1d = TH1 * (float)d;
        float th2d = TH2 * (float)d;
        #pragma unroll
        for (int cc = 0; cc < 2; cc++) {
            float s, co;
            sincosf(th1d * (float)(c0 + cc), &s, &co);
            float u1r = w1 * (co * fr - s * fi);
            float u1i = w1 * (co * fi + s * fr);
            sincosf(th2d * (float)(c0 + cc), &s, &co);
            float u2r = w2 * (co * fr - s * fi);
            float u2i = w2 * (co * fi + s * fr);
            su[cc][d] = make_float4(u1r, u1i, u2r, u2i);
        }
    }

    // ---- side jobs (independent of su) ----
    if (gid < N_TOK) {
        int ci = __ldg(&char_idx[gid]);
        float lam = (float)ci * (1.0f / (float)VOCAB);
        float t = (float)__ldg(&positions[gid]) * 0.01f;
        float omega = 2.0f * PI * 1.5f;
        float kwav = 2.0f * PI / 1.7f;
        float ph1 = omega * t - kwav * lam + 0.8f * lam * lam;
        float ph2 = omega * t * 1.5f - kwav * lam * 0.7f + 0.8f * lam * lam * 1.3f;
        float a1 = sinf(omega * t + 1.5f * lam);
        float a2 = cosf(omega * t * 0.8f + 1.5f * lam * 1.2f);
        float s, cc;
        sincosf(ph1, &s, &cc);
        float wf1r = a1 * cc, wf1i = a1 * s;
        sincosf(ph2, &s, &cc);
        float wf2r = a2 * cc, wf2i = a2 * s;
        g_wf[gid] = make_float4(wf1r, wf1i, wf2r, wf2i);
    }
    if (gid < D) {
        float ph = 2.0f * PI * (float)gid * (1.0f / (float)D);
        float sp, cp, s2p, c2p;
        sincosf(ph, &sp, &cp);
        sincosf(2.0f * ph, &s2p, &c2p);
        g_phtab[gid] = make_float4(cp, sp, c2p, s2p);
        g_cols[gid] = make_float4(__ldg(&bias[gid]), __ldg(&gamma[gid]),
                                  __ldg(&beta_ln[gid]), 0.f);
    }
    if (gid >= 16384 && gid < 16384 + VOCAB) {
        int cc = gid - 16384;
        float cpm = (float)cc * 0.01f;
        float s0, c0_, sb, cb, sc, ccc;
        sincosf(cpm, &s0, &c0_);
        sincosf(cpm * 1.3f, &sb, &cb);
        sincosf(cpm * 0.7f, &sc, &ccc);
        g_tokA[cc] = make_float4(c0_, s0, cb, sb);
        g_tokB[cc] = make_float2(ccc, sc);
    }
    __syncthreads();

    // ---- Gram sums (q == 0 blocks only) ----
    if (q == 0) {
        #pragma unroll
        for (int cc = 0; cc < 2; cc++) {
            float s11 = 0.f, s22 = 0.f, s12r = 0.f, s12i = 0.f;
            #pragma unroll
            for (int l = 0; l < 4; l++) {
                float4 u = su[cc][tid + l * 128];
                s11 += u.x * u.x + u.y * u.y;
                s22 += u.z * u.z + u.w * u.w;
                s12r += u.x * u.z + u.y * u.w;
                s12i += u.y * u.z - u.x * u.w;
            }
            #pragma unroll
            for (int o = 16; o > 0; o >>= 1) {
                s11 += __shfl_xor_sync(0xffffffffu, s11, o);
                s22 += __shfl_xor_sync(0xffffffffu, s22, o);
                s12r += __shfl_xor_sync(0xffffffffu, s12r, o);
                s12i += __shfl_xor_sync(0xffffffffu, s12i, o);
            }
            if ((tid & 31) == 0) {
                int w = tid >> 5;
                smr[0][w] = s11; smr[1][w] = s22; smr[2][w] = s12r; smr[3][w] = s12i;
            }
            __syncthreads();
            if (tid == 0) {
                g_S[c0 + cc] = make_float4(smr[0][0] + smr[0][1] + smr[0][2] + smr[0][3],
                                           smr[1][0] + smr[1][1] + smr[1][2] + smr[1][3],
                                           smr[2][0] + smr[2][1] + smr[2][2] + smr[2][3],
                                           smr[3][0] + smr[3][1] + smr[3][2] + smr[3][3]);
            }
            __syncthreads();
        }
    }

    // ---- tiled GEMM: V[c, q*128+tid], 16 chunks of 32 k-values, 2 chars ----
    const int dpbase = q * 128;
    float a1r = 0.f, a1i = 0.f, a2r = 0.f, a2i = 0.f;
    float b1r = 0.f, b1i = 0.f, b2r = 0.f, b2i = 0.f;

    #pragma unroll 1
    for (int chunk = 0; chunk < 16; chunk++) {
        const int dk = chunk * 32;
        __syncthreads();
        #pragma unroll
        for (int l = 0; l < 8; l++) {
            int f = tid + l * 128;
            int row = f >> 3, col4 = (f & 7) * 4;
            float4 w = *(const float4*)(W + (size_t)(dpbase + row) * D + dk + col4);
            tile[row][col4 + 0] = w.x;
            tile[row][col4 + 1] = w.y;
            tile[row][col4 + 2] = w.z;
            tile[row][col4 + 3] = w.w;
        }
        __syncthreads();
        #pragma unroll
        for (int k = 0; k < 32; k++) {
            float wv = tile[tid][k];
            float4 u = su[0][dk + k];
            float4 v = su[1][dk + k];
            a1r = fmaf(u.x, wv, a1r);
            a1i = fmaf(u.y, wv, a1i);
            a2r = fmaf(u.z, wv, a2r);
            a2i = fmaf(u.w, wv, a2i);
            b1r = fmaf(v.x, wv, b1r);
            b1i = fmaf(v.y, wv, b1i);
            b2r = fmaf(v.z, wv, b2r);
            b2i = fmaf(v.w, wv, b2i);
        }
    }
    g_V[(c0 + 0) * D + dpbase + tid] = make_float4(a1r, a1i, a2r, a2i);
    g_V[(c0 + 1) * D + dpbase + tid] = make_float4(b1r, b1i, b2r, b2i);
}

// ---------------- K1: fused coef + xw + LayerNorm + noise + quaternion ----------
// One token per 128-thread group; 2 tokens per 256-thread block; 5 blocks/SM (R8 shape).
__global__ __launch_bounds__(256, 5) void main_kernel(const int* __restrict__ char_idx,
                                                      const float* __restrict__ noise,
                                                      const float* __restrict__ sem,
                                                      float4* __restrict__ out) {
    __shared__ float red_s[8], red_ss[8];

    const int tid = threadIdx.x;
    const int grp = tid >> 7;
    const int gt = tid & 127;
    const int lane = tid & 31;
    const int wid = tid >> 5;
    const int n = blockIdx.x * 2 + grp;

    // register-resident per-d tables (d = k*128 + gt, fixed per thread)
    float4 colr[4], phr[4];
    #pragma unroll
    for (int k = 0; k < 4; k++) {
        colr[k] = __ldg(&g_cols[k * 128 + gt]);
        phr[k]  = __ldg(&g_phtab[k * 128 + gt]);
    }

    const int c = __ldg(&char_idx[n]);
    const float4 wf = __ldg(&g_wf[n]);
    const float4 S = __ldg(&g_S[c]);

    // per-token coefficients
    float n1 = wf.x * wf.x + wf.y * wf.y;
    float n2 = wf.z * wf.z + wf.w * wf.w;
    float Ar = wf.x * wf.z + wf.y * wf.w;
    float Ai = wf.y * wf.z - wf.x * wf.w;
    float nrm2 = n1 * S.x + n2 * S.y + 2.0f * (Ar * S.z - Ai * S.w);
    float rinv = 1.0f / (sqrtf(nrm2) + 1e-8f);
    const float ct = 0.995004165278025766f;
    const float st = 0.0998334166468281523f;
    const float p1 = (wf.x * ct - wf.y * st) * rinv;
    const float q1 = -(wf.y * ct + wf.x * st) * rinv;
    const float p2 = (wf.z * ct - wf.w * st) * rinv;
    const float q2 = -(wf.w * ct + wf.z * st) * rinv;

    // 4 columns per thread, coalesced V reads; noise prefetched before reduction
    const float4* vrow = g_V + c * D;
    const float* nrow = noise + (size_t)n * D;
    float xw[4], nz[4];
    float s = 0.f, ss = 0.f;
    #pragma unroll
    for (int k = 0; k < 4; k++) {
        const int d = k * 128 + gt;
        float4 v = __ldg(&vrow[d]);
        nz[k] = __ldcs(&nrow[d]);
        float x = fmaf(p1, v.x, fmaf(q1, v.y, fmaf(p2, v.z, q2 * v.w))) + colr[k].x;
        xw[k] = x;
        s += x;
        ss = fmaf(x, x, ss);
    }
    #pragma unroll
    for (int o = 16; o > 0; o >>= 1) {
        s += __shfl_xor_sync(0xffffffffu, s, o);
        ss += __shfl_xor_sync(0xffffffffu, ss, o);
    }
    if (lane == 0) { red_s[wid] = s; red_ss[wid] = ss; }
    __syncthreads();
    const int rb = grp * 4;
    float ts = red_s[rb] + red_s[rb + 1] + red_s[rb + 2] + red_s[rb + 3];
    float tss = red_ss[rb] + red_ss[rb + 1] + red_ss[rb + 2] + red_ss[rb + 3];
    const float mu = ts * (1.0f / (float)D);
    const float rstd = rsqrtf(tss * (1.0f / (float)D) - mu * mu + 1e-5f);

    const float sw0 = __ldg(&sem[c * 4 + 0]);
    const float sw1 = __ldg(&sem[c * 4 + 1]);
    const float sw2 = __ldg(&sem[c * 4 + 2]);
    const float4 tA = __ldg(&g_tokA[c]);
    const float2 tB = __ldg(&g_tokB[c]);

    float4* orow = out + (size_t)n * D;

    #pragma unroll
    for (int k = 0; k < 4; k++) {
        const int d = k * 128 + gt;
        float y = (xw[k] - mu) * rstd * colr[k].y + colr[k].z + 0.01f * nz[k];
        float4 ph = phr[k];
        float4 o;
        o.x = y;
        o.y = y * sw0 * (ph.x * tA.x - ph.y * tA.y);   // cos(phase + cpm)
        o.z = y * sw1 * (ph.y * tA.z + ph.x * tA.w);   // sin(phase + 1.3cpm)
        o.w = y * sw2 * (ph.z * tB.x - ph.w * tB.y);   // cos(2phase + 0.7cpm)
        __stcs(&orow[d], o);
    }
}

// ---------------- launch ----------------
extern "C" void kernel_launch(void* const* d_in, const int* in_sizes, int n_in,
                              void* d_out, int out_size) {
    const int*   char_idx  = (const int*)d_in[0];
    const int*   positions = (const int*)d_in[1];
    const float* W         = (const float*)d_in[2];
    const float* b         = (const float*)d_in[3];
    const float* gamma     = (const float*)d_in[4];
    const float* beta_ln   = (const float*)d_in[5];
    const float* noise     = (const float*)d_in[6];
    const float* sem       = (const float*)d_in[7];
    float4* out = (float4*)d_out;

    prep_kernel<<<dim3(VOCAB / 2, 4), 128>>>(char_idx, positions, W, b, gamma, beta_ln);
    main_kernel<<<N_TOK / 2, 256>>>(char_idx, noise, sem, out);
}

// round 12
// speedup vs baseline: 1.4370x; 1.0884x over previous
#include <cuda_runtime.h>
#include <math.h>
#include <stdint.h>

#define N_TOK 16384
#define D 512
#define VOCAB 96

// ---------------- device scratch ----------------
__device__ float4 g_V[VOCAB * D];    // (V1r, V1i, V2r, V2i) = U @ W^T
__device__ float4 g_S[VOCAB];        // (S11, S22, S12r, S12i)
__device__ float4 g_phtab[D];        // cosP, sinP, cos2P, sin2P
__device__ float4 g_cols[D];         // bias, gamma, beta, 0
__device__ float4 g_wf[N_TOK];       // wf1r, wf1i, wf2r, wf2i
__device__ float4 g_tokA[VOCAB];     // cos(cpm), sin(cpm), cos(1.3cpm), sin(1.3cpm)
__device__ float2 g_tokB[VOCAB];     // cos(.7cpm), sin(.7cpm)

// ---------------- K0: fused prep — U in-block + all tables + V gemm + Gram ----
// grid (48, 4), 128 threads. Block (cg, q): chars {2cg, 2cg+1},
// V columns [q*128, q*128+128). Flat gid covers wf/d-tables/char trig side jobs.
__global__ __launch_bounds__(128) void prep_kernel(const int* __restrict__ char_idx,
                                                   const int* __restrict__ positions,
                                                   const float* __restrict__ W,
                                                   const float* __restrict__ bias,
                                                   const float* __restrict__ gamma,
                                                   const float* __restrict__ beta_ln) {
    const int c0 = blockIdx.x * 2;
    const int q = blockIdx.y;
    const int tid = threadIdx.x;
    const int gid = (blockIdx.y * 48 + blockIdx.x) * 128 + tid;  // 0..24575
    const float PI = 3.14159265358979323846f;
    const float TH1 = 2.0f * PI / ((float)VOCAB * (float)D);
    const float TH2 = 4.0f * PI * 1.7f / ((float)VOCAB * (float)D);

    __shared__ float4 su[2][D];
    __shared__ float tile[128][33];
    __shared__ float smr[4][4];

    // ---- U rows for chars c0, c0+1 (fast trig: all args < ~22 rad) ----
    #pragma unroll
    for (int l = 0; l < 4; l++) {
        const int d = tid + l * 128;
        float kv = (float)d + 1.0f;
        float s1, c1, s2, c2;
        __sincosf(1.5f * atanf(__logf(kv + 1e-10f)), &s1, &c1);
        __sincosf(0.8f * __sinf(0.1f * kv), &s2, &c2);
        float fr = 0.7f * c1 + 0.3f * c2;
        float fi = 0.7f * s1 + 0.3f * s2;
        float w1 = 0.6f + 0.4f * __sinf(0.1f * (float)d);
        float w2 = 0.4f + 0.6f * __cosf(0.15f * (float)d);
        float th1d = TH1 * (float)d;
        float th2d = TH2 * (float)d;
        #pragma unroll
        for (int cc = 0; cc < 2; cc++) {
            float s, co;
            __sincosf(th1d * (float)(c0 + cc), &s, &co);
            float u1r = w1 * (co * fr - s * fi);
            float u1i = w1 * (co * fi + s * fr);
            __sincosf(th2d * (float)(c0 + cc), &s, &co);
            float u2r = w2 * (co * fr - s * fi);
            float u2i = w2 * (co * fi + s * fr);
            su[cc][d] = make_float4(u1r, u1i, u2r, u2i);
        }
    }

    // ---- side jobs ----
    if (gid < N_TOK) {
        // precise trig here: phases reach ~50 rad
        int ci = __ldg(&char_idx[gid]);
        float lam = (float)ci * (1.0f / (float)VOCAB);
        float t = (float)__ldg(&positions[gid]) * 0.01f;
        float omega = 2.0f * PI * 1.5f;
        float kwav = 2.0f * PI / 1.7f;
        float ph1 = omega * t - kwav * lam + 0.8f * lam * lam;
        float ph2 = omega * t * 1.5f - kwav * lam * 0.7f + 0.8f * lam * lam * 1.3f;
        float a1 = sinf(omega * t + 1.5f * lam);
        float a2 = cosf(omega * t * 0.8f + 1.5f * lam * 1.2f);
        float s, cc;
        sincosf(ph1, &s, &cc);
        float wf1r = a1 * cc, wf1i = a1 * s;
        sincosf(ph2, &s, &cc);
        float wf2r = a2 * cc, wf2i = a2 * s;
        g_wf[gid] = make_float4(wf1r, wf1i, wf2r, wf2i);
    }
    if (gid < D) {
        float ph = 2.0f * PI * (float)gid * (1.0f / (float)D);
        float sp, cp, s2p, c2p;
        __sincosf(ph, &sp, &cp);
        __sincosf(2.0f * ph, &s2p, &c2p);
        g_phtab[gid] = make_float4(cp, sp, c2p, s2p);
        g_cols[gid] = make_float4(__ldg(&bias[gid]), __ldg(&gamma[gid]),
                                  __ldg(&beta_ln[gid]), 0.f);
    }
    if (gid >= 16384 && gid < 16384 + VOCAB) {
        int cc = gid - 16384;
        float cpm = (float)cc * 0.01f;
        float s0, c0_, sb, cb, sc, ccc;
        __sincosf(cpm, &s0, &c0_);
        __sincosf(cpm * 1.3f, &sb, &cb);
        __sincosf(cpm * 0.7f, &sc, &ccc);
        g_tokA[cc] = make_float4(c0_, s0, cb, sb);
        g_tokB[cc] = make_float2(ccc, sc);
    }
    __syncthreads();

    // ---- Gram sums (q == 0 blocks only) ----
    if (q == 0) {
        #pragma unroll
        for (int cc = 0; cc < 2; cc++) {
            float s11 = 0.f, s22 = 0.f, s12r = 0.f, s12i = 0.f;
            #pragma unroll
            for (int l = 0; l < 4; l++) {
                float4 u = su[cc][tid + l * 128];
                s11 += u.x * u.x + u.y * u.y;
                s22 += u.z * u.z + u.w * u.w;
                s12r += u.x * u.z + u.y * u.w;
                s12i += u.y * u.z - u.x * u.w;
            }
            #pragma unroll
            for (int o = 16; o > 0; o >>= 1) {
                s11 += __shfl_xor_sync(0xffffffffu, s11, o);
                s22 += __shfl_xor_sync(0xffffffffu, s22, o);
                s12r += __shfl_xor_sync(0xffffffffu, s12r, o);
                s12i += __shfl_xor_sync(0xffffffffu, s12i, o);
            }
            if ((tid & 31) == 0) {
                int w = tid >> 5;
                smr[0][w] = s11; smr[1][w] = s22; smr[2][w] = s12r; smr[3][w] = s12i;
            }
            __syncthreads();
            if (tid == 0) {
                g_S[c0 + cc] = make_float4(smr[0][0] + smr[0][1] + smr[0][2] + smr[0][3],
                                           smr[1][0] + smr[1][1] + smr[1][2] + smr[1][3],
                                           smr[2][0] + smr[2][1] + smr[2][2] + smr[2][3],
                                           smr[3][0] + smr[3][1] + smr[3][2] + smr[3][3]);
            }
            __syncthreads();
        }
    }

    // ---- tiled GEMM: V[c, q*128+tid], 16 chunks of 32 k-values, 2 chars ----
    const int dpbase = q * 128;
    float a1r = 0.f, a1i = 0.f, a2r = 0.f, a2i = 0.f;
    float b1r = 0.f, b1i = 0.f, b2r = 0.f, b2i = 0.f;

    #pragma unroll 1
    for (int chunk = 0; chunk < 16; chunk++) {
        const int dk = chunk * 32;
        __syncthreads();
        #pragma unroll
        for (int l = 0; l < 8; l++) {
            int f = tid + l * 128;
            int row = f >> 3, col4 = (f & 7) * 4;
            float4 w = *(const float4*)(W + (size_t)(dpbase + row) * D + dk + col4);
            tile[row][col4 + 0] = w.x;
            tile[row][col4 + 1] = w.y;
            tile[row][col4 + 2] = w.z;
            tile[row][col4 + 3] = w.w;
        }
        __syncthreads();
        #pragma unroll
        for (int k = 0; k < 32; k++) {
            float wv = tile[tid][k];
            float4 u = su[0][dk + k];
            float4 v = su[1][dk + k];
            a1r = fmaf(u.x, wv, a1r);
            a1i = fmaf(u.y, wv, a1i);
            a2r = fmaf(u.z, wv, a2r);
            a2i = fmaf(u.w, wv, a2i);
            b1r = fmaf(v.x, wv, b1r);
            b1i = fmaf(v.y, wv, b1i);
            b2r = fmaf(v.z, wv, b2r);
            b2i = fmaf(v.w, wv, b2i);
        }
    }
    g_V[(c0 + 0) * D + dpbase + tid] = make_float4(a1r, a1i, a2r, a2i);
    g_V[(c0 + 1) * D + dpbase + tid] = make_float4(b1r, b1i, b2r, b2i);
}

// ---------------- K1: fused coef + xw + LayerNorm + noise + quaternion ----------
// 128-thread group processes 4 tokens sequentially (tables amortized in regs);
// 2 groups per 256-thread block -> 8 tokens/block, grid = N_TOK/8.
__global__ __launch_bounds__(256, 4) void main_kernel(const int* __restrict__ char_idx,
                                                      const float* __restrict__ noise,
                                                      const float* __restrict__ sem,
                                                      float4* __restrict__ out) {
    __shared__ float red_s[8], red_ss[8];

    const int tid = threadIdx.x;
    const int grp = tid >> 7;
    const int gt = tid & 127;
    const int lane = tid & 31;
    const int wid = tid >> 5;          // 0..7 block-wide
    const int nbase = blockIdx.x * 8 + grp * 4;

    // register-resident per-d tables (d = k*128 + gt), loaded ONCE for 4 tokens
    float4 colr[4], phr[4];
    #pragma unroll
    for (int k = 0; k < 4; k++) {
        colr[k] = __ldg(&g_cols[k * 128 + gt]);
        phr[k]  = __ldg(&g_phtab[k * 128 + gt]);
    }

    const float ct = 0.995004165278025766f;
    const float st = 0.0998334166468281523f;

    #pragma unroll 1
    for (int t = 0; t < 4; t++) {
        const int n = nbase + t;
        const int c = __ldg(&char_idx[n]);
        const float4 wf = __ldg(&g_wf[n]);
        const float4 S = __ldg(&g_S[c]);

        float n1 = wf.x * wf.x + wf.y * wf.y;
        float n2 = wf.z * wf.z + wf.w * wf.w;
        float Ar = wf.x * wf.z + wf.y * wf.w;
        float Ai = wf.y * wf.z - wf.x * wf.w;
        float nrm2 = n1 * S.x + n2 * S.y + 2.0f * (Ar * S.z - Ai * S.w);
        float rinv = 1.0f / (sqrtf(nrm2) + 1e-8f);
        const float p1 = (wf.x * ct - wf.y * st) * rinv;
        const float q1 = -(wf.y * ct + wf.x * st) * rinv;
        const float p2 = (wf.z * ct - wf.w * st) * rinv;
        const float q2 = -(wf.w * ct + wf.z * st) * rinv;

        const float4* vrow = g_V + c * D;
        const float* nrow = noise + (size_t)n * D;
        float xw[4], nz[4];
        float s = 0.f, ss = 0.f;
        #pragma unroll
        for (int k = 0; k < 4; k++) {
            const int d = k * 128 + gt;
            float4 v = __ldg(&vrow[d]);
            nz[k] = __ldcs(&nrow[d]);
            float x = fmaf(p1, v.x, fmaf(q1, v.y, fmaf(p2, v.z, q2 * v.w))) + colr[k].x;
            xw[k] = x;
            s += x;
            ss = fmaf(x, x, ss);
        }
        #pragma unroll
        for (int o = 16; o > 0; o >>= 1) {
            s += __shfl_xor_sync(0xffffffffu, s, o);
            ss += __shfl_xor_sync(0xffffffffu, ss, o);
        }
        __syncthreads();                 // previous iteration's reads complete
        if (lane == 0) { red_s[wid] = s; red_ss[wid] = ss; }
        __syncthreads();
        const int rb = grp * 4;
        float ts = red_s[rb] + red_s[rb + 1] + red_s[rb + 2] + red_s[rb + 3];
        float tss = red_ss[rb] + red_ss[rb + 1] + red_ss[rb + 2] + red_ss[rb + 3];
        const float mu = ts * (1.0f / (float)D);
        const float rstd = rsqrtf(tss * (1.0f / (float)D) - mu * mu + 1e-5f);

        const float sw0 = __ldg(&sem[c * 4 + 0]);
        const float sw1 = __ldg(&sem[c * 4 + 1]);
        const float sw2 = __ldg(&sem[c * 4 + 2]);
        const float4 tA = __ldg(&g_tokA[c]);
        const float2 tB = __ldg(&g_tokB[c]);

        float4* orow = out + (size_t)n * D;
        #pragma unroll
        for (int k = 0; k < 4; k++) {
            const int d = k * 128 + gt;
            float y = (xw[k] - mu) * rstd * colr[k].y + colr[k].z + 0.01f * nz[k];
            float4 ph = phr[k];
            float4 o;
            o.x = y;
            o.y = y * sw0 * (ph.x * tA.x - ph.y * tA.y);   // cos(phase + cpm)
            o.z = y * sw1 * (ph.y * tA.z + ph.x * tA.w);   // sin(phase + 1.3cpm)
            o.w = y * sw2 * (ph.z * tB.x - ph.w * tB.y);   // cos(2phase + 0.7cpm)
            __stcs(&orow[d], o);
        }
    }
}

// ---------------- launch ----------------
extern "C" void kernel_launch(void* const* d_in, const int* in_sizes, int n_in,
                              void* d_out, int out_size) {
    const int*   char_idx  = (const int*)d_in[0];
    const int*   positions = (const int*)d_in[1];
    const float* W         = (const float*)d_in[2];
    const float* b         = (const float*)d_in[3];
    const float* gamma     = (const float*)d_in[4];
    const float* beta_ln   = (const float*)d_in[5];
    const float* noise     = (const float*)d_in[6];
    const float* sem       = (const float*)d_in[7];
    float4* out = (float4*)d_out;

    prep_kernel<<<dim3(VOCAB / 2, 4), 128>>>(char_idx, positions, W, b, gamma, beta_ln);
    main_kernel<<<N_TOK / 8, 256>>>(char_idx, noise, sem, out);
}